// round 3
// baseline (speedup 1.0000x reference)
#include <cuda_runtime.h>
#include <cuda_bf16.h>
#include <math.h>

// Problem constants
#define TOK   8192      // B*S
#define SEQ   4096
#define BATCH 2
#define HIDN  768
#define FFN   3072
#define NHEAD 12
#define HD    64
#define WIN   128       // one-sided window W
#define NCH   32        // SEQ / WIN
#define NLAYER 4

// ---------------- scratch (no allocation allowed; __device__ globals) -------
__device__ float g_h[TOK * HIDN];
__device__ float g_q[TOK * HIDN];
__device__ float g_k[TOK * HIDN];
__device__ float g_v[TOK * HIDN];
__device__ float g_a[TOK * HIDN];
__device__ float g_t[TOK * HIDN];
__device__ float g_f[TOK * FFN];

// ---------------- block-wide allreduce of two floats (256 threads) ---------
__device__ __forceinline__ void block_allreduce2(float& a, float& b) {
    __shared__ float sa[8], sb[8];
    int lane = threadIdx.x & 31, w = threadIdx.x >> 5;
#pragma unroll
    for (int o = 16; o > 0; o >>= 1) {
        a += __shfl_down_sync(0xffffffffu, a, o);
        b += __shfl_down_sync(0xffffffffu, b, o);
    }
    if (lane == 0) { sa[w] = a; sb[w] = b; }
    __syncthreads();
    if (w == 0) {
        a = (lane < 8) ? sa[lane] : 0.f;
        b = (lane < 8) ? sb[lane] : 0.f;
#pragma unroll
        for (int o = 4; o > 0; o >>= 1) {
            a += __shfl_down_sync(0xffffffffu, a, o);
            b += __shfl_down_sync(0xffffffffu, b, o);
        }
        if (lane == 0) { sa[0] = a; sb[0] = b; }
    }
    __syncthreads();
    a = sa[0]; b = sb[0];
}

// ---------------- embeddings + LayerNorm ------------------------------------
// h = LN(emb + pos_emb[s+1] + tok_emb[0]) * g + b    (one block per token)
__global__ __launch_bounds__(256) void embed_ln_kernel(
    const float* __restrict__ emb, const float* __restrict__ pos,
    const float* __restrict__ tok, const float* __restrict__ g,
    const float* __restrict__ be)
{
    int t = blockIdx.x;
    int s = t & (SEQ - 1);
    int tid = threadIdx.x;
    float v[3];
    float su = 0.f, sq = 0.f;
#pragma unroll
    for (int i = 0; i < 3; ++i) {
        int c = tid + i * 256;
        float z = emb[(size_t)t * HIDN + c] + pos[(size_t)(s + 1) * HIDN + c] + tok[c];
        v[i] = z; su += z; sq += z * z;
    }
    block_allreduce2(su, sq);
    float mean = su * (1.f / HIDN);
    float var  = fmaxf(sq * (1.f / HIDN) - mean * mean, 0.f);
    float rstd = rsqrtf(var + 1e-12f);
#pragma unroll
    for (int i = 0; i < 3; ++i) {
        int c = tid + i * 256;
        g_h[(size_t)t * HIDN + c] = (v[i] - mean) * rstd * g[c] + be[c];
    }
}

// ---------------- out = LN(x + y) * gamma + beta ----------------------------
__global__ __launch_bounds__(256) void add_ln_kernel(
    const float* __restrict__ x, const float* __restrict__ y,
    const float* __restrict__ gamma, const float* __restrict__ beta,
    float* __restrict__ out)
{
    int t = blockIdx.x;
    int tid = threadIdx.x;
    float v[3];
    float su = 0.f, sq = 0.f;
#pragma unroll
    for (int i = 0; i < 3; ++i) {
        int c = tid + i * 256;
        float z = x[(size_t)t * HIDN + c] + y[(size_t)t * HIDN + c];
        v[i] = z; su += z; sq += z * z;
    }
    block_allreduce2(su, sq);
    float mean = su * (1.f / HIDN);
    float var  = fmaxf(sq * (1.f / HIDN) - mean * mean, 0.f);
    float rstd = rsqrtf(var + 1e-12f);
#pragma unroll
    for (int i = 0; i < 3; ++i) {
        int c = tid + i * 256;
        out[(size_t)t * HIDN + c] = (v[i] - mean) * rstd * gamma[c] + beta[c];
    }
}

// ---------------- SGEMM: C[M,N] = A[M,K] @ B[K,N] + bias (opt. GELU) --------
// 128x128 tile, BK=8, 256 threads, 8x8 microtile, global prefetch.
// All dims guaranteed multiples of tile sizes; no bounds checks.
#define BM 128
#define BN 128
#define BK 8

template <int ACT>
__global__ __launch_bounds__(256) void sgemm_kernel(
    const float* __restrict__ A, const float* __restrict__ Bm,
    const float* __restrict__ bias, float* __restrict__ C,
    int M, int N, int K)
{
    __shared__ float As[BK][BM];
    __shared__ float Bs[BK][BN];
    int tid = threadIdx.x;
    int row0 = blockIdx.y * BM;
    int col0 = blockIdx.x * BN;
    int tx = tid & 15, ty = tid >> 4;

    int ar = tid >> 1;           // 0..127
    int ac = (tid & 1) * 4;      // 0 or 4
    int br = tid >> 5;           // 0..7
    int bc = (tid & 31) * 4;     // 0..124

    const float* Aptr = A + (size_t)(row0 + ar) * K + ac;
    const float* Bptr = Bm + (size_t)br * N + col0 + bc;

    float acc[8][8];
#pragma unroll
    for (int i = 0; i < 8; ++i)
#pragma unroll
        for (int j = 0; j < 8; ++j) acc[i][j] = 0.f;

    float4 a4 = *(const float4*)(Aptr);
    float4 b4 = *(const float4*)(Bptr);

    for (int k0 = 0; k0 < K; k0 += BK) {
        As[ac + 0][ar] = a4.x; As[ac + 1][ar] = a4.y;
        As[ac + 2][ar] = a4.z; As[ac + 3][ar] = a4.w;
        *(float4*)(&Bs[br][bc]) = b4;
        __syncthreads();
        if (k0 + BK < K) {
            a4 = *(const float4*)(Aptr + k0 + BK);
            b4 = *(const float4*)(Bptr + (size_t)(k0 + BK) * N);
        }
#pragma unroll
        for (int k = 0; k < BK; ++k) {
            float a[8], b[8];
            *(float4*)(a)     = *(const float4*)(&As[k][ty * 8]);
            *(float4*)(a + 4) = *(const float4*)(&As[k][ty * 8 + 4]);
            *(float4*)(b)     = *(const float4*)(&Bs[k][tx * 8]);
            *(float4*)(b + 4) = *(const float4*)(&Bs[k][tx * 8 + 4]);
#pragma unroll
            for (int i = 0; i < 8; ++i)
#pragma unroll
                for (int j = 0; j < 8; ++j)
                    acc[i][j] = fmaf(a[i], b[j], acc[i][j]);
        }
        __syncthreads();
    }

#pragma unroll
    for (int i = 0; i < 8; ++i) {
        int r = row0 + ty * 8 + i;
        float* Crow = C + (size_t)r * N + col0 + tx * 8;
#pragma unroll
        for (int j = 0; j < 8; j += 4) {
            float4 o;
            float x0 = acc[i][j + 0] + bias[col0 + tx * 8 + j + 0];
            float x1 = acc[i][j + 1] + bias[col0 + tx * 8 + j + 1];
            float x2 = acc[i][j + 2] + bias[col0 + tx * 8 + j + 2];
            float x3 = acc[i][j + 3] + bias[col0 + tx * 8 + j + 3];
            if (ACT == 1) {  // exact GELU
                x0 = 0.5f * x0 * (1.f + erff(x0 * 0.70710678118654752f));
                x1 = 0.5f * x1 * (1.f + erff(x1 * 0.70710678118654752f));
                x2 = 0.5f * x2 * (1.f + erff(x2 * 0.70710678118654752f));
                x3 = 0.5f * x3 * (1.f + erff(x3 * 0.70710678118654752f));
            }
            o.x = x0; o.y = x1; o.z = x2; o.w = x3;
            *(float4*)(Crow + j) = o;
        }
    }
}

// ---------------- sliding-window attention ----------------------------------
// Block = (chunk c, head, batch), 128 threads = 128 queries of the chunk.
// Keys iterate over six 64-row tiles covering [c*W - W, c*W + 2W). Band
// condition |kpos - qpos| <= W, key_mask, online softmax (identical to the
// reference's -1e9 masking: exp(-1e9 - max) == 0 in fp32).
__global__ __launch_bounds__(128) void attention_kernel(
    const float* __restrict__ q, const float* __restrict__ k,
    const float* __restrict__ v, const int* __restrict__ amask,
    float* __restrict__ o)
{
    __shared__ float ks[64 * 64];
    __shared__ float vs[64 * 64];
    __shared__ int   km[64];

    int c  = blockIdx.x;
    int hh = blockIdx.y;
    int b  = blockIdx.z;
    int p  = threadIdx.x;
    int qpos = c * WIN + p;

    float qr[64];
    {
        const float4* q4 = (const float4*)(q + (size_t)(b * SEQ + qpos) * HIDN + hh * HD);
#pragma unroll
        for (int i = 0; i < 16; ++i) {
            float4 t4 = q4[i];
            qr[4 * i + 0] = t4.x * 0.125f;   // 1/sqrt(64)
            qr[4 * i + 1] = t4.y * 0.125f;
            qr[4 * i + 2] = t4.z * 0.125f;
            qr[4 * i + 3] = t4.w * 0.125f;
        }
    }

    float m = -1e30f, l = 0.f;
    float acc[64];
#pragma unroll
    for (int i = 0; i < 64; ++i) acc[i] = 0.f;

    int lo = qpos - WIN, hi = qpos + WIN;
    int kstart = c * WIN - WIN;

    for (int t = 0; t < 6; ++t) {
        int kbase = kstart + t * 64;
        if (kbase < 0 || kbase >= SEQ) continue;   // uniform across block
        __syncthreads();
        for (int i = p; i < 64 * 16; i += 128) {
            int jj = i >> 4;
            int d4 = (i & 15) << 2;
            size_t gofs = (size_t)(b * SEQ + kbase + jj) * HIDN + hh * HD + d4;
            *(float4*)(ks + jj * 64 + d4) = *(const float4*)(k + gofs);
            *(float4*)(vs + jj * 64 + d4) = *(const float4*)(v + gofs);
        }
        if (p < 64) km[p] = amask[b * SEQ + kbase + p];
        __syncthreads();

        for (int jj = 0; jj < 64; ++jj) {
            int kpos = kbase + jj;
            const float4* k4 = (const float4*)(ks + jj * 64);
            float s = 0.f;
#pragma unroll
            for (int i = 0; i < 16; ++i) {
                float4 kk = k4[i];
                s = fmaf(qr[4 * i + 0], kk.x, s);
                s = fmaf(qr[4 * i + 1], kk.y, s);
                s = fmaf(qr[4 * i + 2], kk.z, s);
                s = fmaf(qr[4 * i + 3], kk.w, s);
            }
            if (kpos < lo || kpos > hi || km[jj] == 0) continue;
            const float4* v4 = (const float4*)(vs + jj * 64);
            if (s > m) {
                float r = __expf(m - s);
                m = s;
                l = fmaf(l, r, 1.f);
#pragma unroll
                for (int i = 0; i < 16; ++i) {
                    float4 vv = v4[i];
                    acc[4 * i + 0] = fmaf(acc[4 * i + 0], r, vv.x);
                    acc[4 * i + 1] = fmaf(acc[4 * i + 1], r, vv.y);
                    acc[4 * i + 2] = fmaf(acc[4 * i + 2], r, vv.z);
                    acc[4 * i + 3] = fmaf(acc[4 * i + 3], r, vv.w);
                }
            } else {
                float pe = __expf(s - m);
                l += pe;
#pragma unroll
                for (int i = 0; i < 16; ++i) {
                    float4 vv = v4[i];
                    acc[4 * i + 0] = fmaf(pe, vv.x, acc[4 * i + 0]);
                    acc[4 * i + 1] = fmaf(pe, vv.y, acc[4 * i + 1]);
                    acc[4 * i + 2] = fmaf(pe, vv.z, acc[4 * i + 2]);
                    acc[4 * i + 3] = fmaf(pe, vv.w, acc[4 * i + 3]);
                }
            }
        }
    }

    float inv = 1.f / l;
    float4* o4 = (float4*)(o + (size_t)(b * SEQ + qpos) * HIDN + hh * HD);
#pragma unroll
    for (int i = 0; i < 16; ++i) {
        float4 t4;
        t4.x = acc[4 * i + 0] * inv;
        t4.y = acc[4 * i + 1] * inv;
        t4.z = acc[4 * i + 2] * inv;
        t4.w = acc[4 * i + 3] * inv;
        o4[i] = t4;
    }
}

// ---------------- classifier: sigmoid(h @ Wp + bp) --------------------------
__global__ __launch_bounds__(256) void classifier_kernel(
    const float* __restrict__ Wp, const float* __restrict__ bp,
    float* __restrict__ out)
{
    int t = blockIdx.x, tid = threadIdx.x;
    float s = 0.f, dummy = 0.f;
#pragma unroll
    for (int i = 0; i < 3; ++i) {
        int c = tid + i * 256;
        s += g_h[(size_t)t * HIDN + c] * Wp[c];
    }
    block_allreduce2(s, dummy);
    if (tid == 0) out[t] = 1.f / (1.f + expf(-(s + bp[0])));
}

// ---------------- host launcher ---------------------------------------------
extern "C" void kernel_launch(void* const* d_in, const int* in_sizes, int n_in,
                              void* d_out, int out_size)
{
    (void)in_sizes; (void)n_in; (void)out_size;
    const float* emb  = (const float*)d_in[0];
    const int*   amask= (const int*)  d_in[1];
    const float* pos  = (const float*)d_in[2];
    const float* tok  = (const float*)d_in[3];
    const float* elng = (const float*)d_in[4];
    const float* elnb = (const float*)d_in[5];
    const float* Wq = (const float*)d_in[6],  *bq = (const float*)d_in[7];
    const float* Wk = (const float*)d_in[8],  *bk = (const float*)d_in[9];
    const float* Wv = (const float*)d_in[10], *bv = (const float*)d_in[11];
    const float* Wo = (const float*)d_in[12], *bo = (const float*)d_in[13];
    const float* ln1g = (const float*)d_in[14], *ln1b = (const float*)d_in[15];
    const float* Wi = (const float*)d_in[16], *bi = (const float*)d_in[17];
    const float* Wf = (const float*)d_in[18], *bf = (const float*)d_in[19];
    const float* ln2g = (const float*)d_in[20], *ln2b = (const float*)d_in[21];
    const float* Wp = (const float*)d_in[22], *bp = (const float*)d_in[23];

    float *ph, *pq, *pk, *pv, *pa, *pt, *pf;
    cudaGetSymbolAddress((void**)&ph, g_h);
    cudaGetSymbolAddress((void**)&pq, g_q);
    cudaGetSymbolAddress((void**)&pk, g_k);
    cudaGetSymbolAddress((void**)&pv, g_v);
    cudaGetSymbolAddress((void**)&pa, g_a);
    cudaGetSymbolAddress((void**)&pt, g_t);
    cudaGetSymbolAddress((void**)&pf, g_f);

    embed_ln_kernel<<<TOK, 256>>>(emb, pos, tok, elng, elnb);

    dim3 gH(HIDN / BN, TOK / BM);   // (6, 64)
    dim3 gF(FFN / BN, TOK / BM);    // (24, 64)

    for (int l = 0; l < NLAYER; ++l) {
        const float* wq = Wq + (size_t)l * HIDN * HIDN;
        const float* wk = Wk + (size_t)l * HIDN * HIDN;
        const float* wv = Wv + (size_t)l * HIDN * HIDN;
        const float* wo = Wo + (size_t)l * HIDN * HIDN;
        const float* wi = Wi + (size_t)l * HIDN * FFN;
        const float* wf = Wf + (size_t)l * FFN * HIDN;

        sgemm_kernel<0><<<gH, 256>>>(ph, wq, bq + l * HIDN, pq, TOK, HIDN, HIDN);
        sgemm_kernel<0><<<gH, 256>>>(ph, wk, bk + l * HIDN, pk, TOK, HIDN, HIDN);
        sgemm_kernel<0><<<gH, 256>>>(ph, wv, bv + l * HIDN, pv, TOK, HIDN, HIDN);

        attention_kernel<<<dim3(NCH, NHEAD, BATCH), 128>>>(pq, pk, pv, amask, pa);

        sgemm_kernel<0><<<gH, 256>>>(pa, wo, bo + l * HIDN, pt, TOK, HIDN, HIDN);
        add_ln_kernel<<<TOK, 256>>>(ph, pt, ln1g + l * HIDN, ln1b + l * HIDN, ph);

        sgemm_kernel<1><<<gF, 256>>>(ph, wi, bi + l * FFN, pf, TOK, FFN, HIDN);
        sgemm_kernel<0><<<gH, 256>>>(pf, wf, bf + l * HIDN, pt, TOK, HIDN, FFN);
        add_ln_kernel<<<TOK, 256>>>(ph, pt, ln2g + l * HIDN, ln2b + l * HIDN, ph);
    }

    classifier_kernel<<<TOK, 256>>>(Wp, bp, (float*)d_out);
}

// round 5
// speedup vs baseline: 2.0948x; 2.0948x over previous
#include <cuda_runtime.h>
#include <cuda_bf16.h>
#include <math.h>
#include <stdint.h>

// Problem constants
#define TOK   8192      // B*S
#define SEQ   4096
#define BATCH 2
#define HIDN  768
#define FFN   3072
#define NHEAD 12
#define HD    64
#define WIN   128
#define NCH   32
#define NLAYER 4
#define QKVN  2304      // fused QKV output width

// per-layer transposed-weight layout (elements)
#define OFF_QKV 0
#define OFF_O   1769472          // 2304*768
#define OFF_I   2359296          // + 768*768
#define OFF_F   4718592          // + 3072*768
#define LW      7077888          // + 768*3072
#define WTOT    (NLAYER * LW)

// ---------------- scratch ----------------------------------------------------
__device__ float g_h[TOK * HIDN];
__device__ float g_qkv[TOK * QKVN];
__device__ float g_a[TOK * HIDN];
__device__ float g_t[TOK * HIDN];
__device__ float g_f[TOK * FFN];
__device__ __nv_bfloat16 g_xh[TOK * FFN];
__device__ __nv_bfloat16 g_xl[TOK * FFN];
__device__ __nv_bfloat16 g_wh[WTOT];
__device__ __nv_bfloat16 g_wl[WTOT];
__device__ float g_bqkv[NLAYER * QKVN];

// ---------------- PTX helpers ------------------------------------------------
__device__ __forceinline__ uint32_t smem_u32(const void* p) {
    uint32_t a;
    asm("{ .reg .u64 t; cvta.to.shared.u64 t, %1; cvt.u32.u64 %0, t; }" : "=r"(a) : "l"(p));
    return a;
}
__device__ __forceinline__ void cpasync16(uint32_t dst, const void* src) {
    asm volatile("cp.async.cg.shared.global [%0], [%1], 16;" :: "r"(dst), "l"(src));
}
#define CP_COMMIT() asm volatile("cp.async.commit_group;" ::: "memory")
#define CP_WAIT0()  asm volatile("cp.async.wait_group 0;" ::: "memory")
#define CP_WAIT1()  asm volatile("cp.async.wait_group 1;" ::: "memory")

__device__ __forceinline__ void ldsm4(uint32_t* r, uint32_t addr) {
    asm volatile("ldmatrix.sync.aligned.m8n8.x4.shared.b16 {%0,%1,%2,%3}, [%4];"
                 : "=r"(r[0]), "=r"(r[1]), "=r"(r[2]), "=r"(r[3]) : "r"(addr));
}
__device__ __forceinline__ void mma16816(float* d, const uint32_t* a, const uint32_t* b) {
    asm volatile("mma.sync.aligned.m16n8k16.row.col.f32.bf16.bf16.f32 "
                 "{%0,%1,%2,%3}, {%4,%5,%6,%7}, {%8,%9}, {%0,%1,%2,%3};"
                 : "+f"(d[0]), "+f"(d[1]), "+f"(d[2]), "+f"(d[3])
                 : "r"(a[0]), "r"(a[1]), "r"(a[2]), "r"(a[3]), "r"(b[0]), "r"(b[1]));
}

// ---------------- block-wide allreduce of two floats (256 threads) -----------
__device__ __forceinline__ void block_allreduce2(float& a, float& b) {
    __shared__ float sa[8], sb[8];
    int lane = threadIdx.x & 31, w = threadIdx.x >> 5;
#pragma unroll
    for (int o = 16; o > 0; o >>= 1) {
        a += __shfl_down_sync(0xffffffffu, a, o);
        b += __shfl_down_sync(0xffffffffu, b, o);
    }
    if (lane == 0) { sa[w] = a; sb[w] = b; }
    __syncthreads();
    if (w == 0) {
        a = (lane < 8) ? sa[lane] : 0.f;
        b = (lane < 8) ? sb[lane] : 0.f;
#pragma unroll
        for (int o = 4; o > 0; o >>= 1) {
            a += __shfl_down_sync(0xffffffffu, a, o);
            b += __shfl_down_sync(0xffffffffu, b, o);
        }
        if (lane == 0) { sa[0] = a; sb[0] = b; }
    }
    __syncthreads();
    a = sa[0]; b = sb[0];
}

// ---------------- elementwise kernels ----------------------------------------
__global__ __launch_bounds__(256) void embed_ln_kernel(
    const float* __restrict__ emb, const float* __restrict__ pos,
    const float* __restrict__ tok, const float* __restrict__ g,
    const float* __restrict__ be)
{
    int t = blockIdx.x;
    int s = t & (SEQ - 1);
    int tid = threadIdx.x;
    float v[3];
    float su = 0.f, sq = 0.f;
#pragma unroll
    for (int i = 0; i < 3; ++i) {
        int c = tid + i * 256;
        float z = emb[(size_t)t * HIDN + c] + pos[(size_t)(s + 1) * HIDN + c] + tok[c];
        v[i] = z; su += z; sq += z * z;
    }
    block_allreduce2(su, sq);
    float mean = su * (1.f / HIDN);
    float var  = fmaxf(sq * (1.f / HIDN) - mean * mean, 0.f);
    float rstd = rsqrtf(var + 1e-12f);
#pragma unroll
    for (int i = 0; i < 3; ++i) {
        int c = tid + i * 256;
        g_h[(size_t)t * HIDN + c] = (v[i] - mean) * rstd * g[c] + be[c];
    }
}

__global__ __launch_bounds__(256) void add_ln_kernel(
    const float* __restrict__ x, const float* __restrict__ y,
    const float* __restrict__ gamma, const float* __restrict__ beta,
    float* __restrict__ out)
{
    int t = blockIdx.x;
    int tid = threadIdx.x;
    float v[3];
    float su = 0.f, sq = 0.f;
#pragma unroll
    for (int i = 0; i < 3; ++i) {
        int c = tid + i * 256;
        float z = x[(size_t)t * HIDN + c] + y[(size_t)t * HIDN + c];
        v[i] = z; su += z; sq += z * z;
    }
    block_allreduce2(su, sq);
    float mean = su * (1.f / HIDN);
    float var  = fmaxf(sq * (1.f / HIDN) - mean * mean, 0.f);
    float rstd = rsqrtf(var + 1e-12f);
#pragma unroll
    for (int i = 0; i < 3; ++i) {
        int c = tid + i * 256;
        out[(size_t)t * HIDN + c] = (v[i] - mean) * rstd * gamma[c] + beta[c];
    }
}

// split fp32 -> (hi, lo) bf16, elementwise, vectorized by 4
__global__ __launch_bounds__(256) void asplit_kernel(
    const float* __restrict__ X, __nv_bfloat16* __restrict__ Xh,
    __nv_bfloat16* __restrict__ Xl, int n4)
{
    int i = blockIdx.x * 256 + threadIdx.x;
    if (i >= n4) return;
    float4 x = ((const float4*)X)[i];
    float v[4] = {x.x, x.y, x.z, x.w};
    __nv_bfloat16 h[4], l[4];
#pragma unroll
    for (int j = 0; j < 4; ++j) {
        h[j] = __float2bfloat16(v[j]);
        l[j] = __float2bfloat16(v[j] - __bfloat162float(h[j]));
    }
    __nv_bfloat162 p0, p1, q0, q1;
    p0.x = h[0]; p0.y = h[1]; p1.x = h[2]; p1.y = h[3];
    q0.x = l[0]; q0.y = l[1]; q1.x = l[2]; q1.y = l[3];
    ((__nv_bfloat162*)Xh)[2 * i] = p0; ((__nv_bfloat162*)Xh)[2 * i + 1] = p1;
    ((__nv_bfloat162*)Xl)[2 * i] = q0; ((__nv_bfloat162*)Xl)[2 * i + 1] = q1;
}

// transpose + split: W fp32 [K,N] row-major -> Th/Tl bf16 [N,K] row-major
__global__ __launch_bounds__(256) void wsplit_t_kernel(
    const float* __restrict__ W, __nv_bfloat16* __restrict__ Th,
    __nv_bfloat16* __restrict__ Tl, int K, int N)
{
    __shared__ float tile[32][33];
    int nb = blockIdx.x * 32, kb = blockIdx.y * 32;
    int tx = threadIdx.x & 31, ty = threadIdx.x >> 5;   // 32 x 8
#pragma unroll
    for (int i = 0; i < 32; i += 8)
        tile[ty + i][tx] = W[(size_t)(kb + ty + i) * N + nb + tx];
    __syncthreads();
#pragma unroll
    for (int i = 0; i < 32; i += 8) {
        float x = tile[tx][ty + i];
        __nv_bfloat16 h = __float2bfloat16(x);
        __nv_bfloat16 l = __float2bfloat16(x - __bfloat162float(h));
        size_t o = (size_t)(nb + ty + i) * K + kb + tx;
        Th[o] = h; Tl[o] = l;
    }
}

// concat QKV biases per layer into g_bqkv
__global__ __launch_bounds__(256) void bqkv_kernel(
    const float* __restrict__ bq, const float* __restrict__ bk, const float* __restrict__ bv)
{
    int i = blockIdx.x * 256 + threadIdx.x;
    if (i >= NLAYER * QKVN) return;
    int l = i / QKVN, c = i - l * QKVN;
    float v = (c < 768) ? bq[l * 768 + c] : (c < 1536) ? bk[l * 768 + c - 768] : bv[l * 768 + c - 1536];
    g_bqkv[i] = v;
}

// ---------------- HMMA split-bf16 GEMM ---------------------------------------
// C[M,N] = Ahi/lo[M,K] * (Bhi/lo[N,K])^T + bias, fp32 out, 3-pass Markidis.
// CTA 128x128, BK=32, 256 threads (2x4 warps, 64x32 warp tile), cp.async
// double buffer. Row padding 40 bf16 (80B) -> conflict-free ldmatrix phases.
#define PADR 40
#define TILE_E (128 * PADR)           // elems per operand tile
#define STAGE_E (4 * TILE_E)          // Ah, Al, Bh, Bl
#define GEMM_SMEM_B (2 * STAGE_E * 2) // 81920 bytes

__device__ __forceinline__ void gemm_load_stage(
    uint32_t sbase, int s, int kt, int row0, int col0, int tid, int K,
    const __nv_bfloat16* __restrict__ Ah, const __nv_bfloat16* __restrict__ Al,
    const __nv_bfloat16* __restrict__ Bh, const __nv_bfloat16* __restrict__ Bl)
{
    int k0 = kt * 32;
    uint32_t so = sbase + (uint32_t)s * STAGE_E * 2;
#pragma unroll
    for (int t = 0; t < 2; ++t) {
        int id = tid + t * 256;
        int r = id >> 2, c8 = (id & 3) * 8;
        uint32_t doff = (uint32_t)(r * PADR + c8) * 2;
        size_t ga = (size_t)(row0 + r) * K + k0 + c8;
        size_t gb = (size_t)(col0 + r) * K + k0 + c8;
        cpasync16(so + 0 * TILE_E * 2 + doff, Ah + ga);
        cpasync16(so + 1 * TILE_E * 2 + doff, Al + ga);
        cpasync16(so + 2 * TILE_E * 2 + doff, Bh + gb);
        cpasync16(so + 3 * TILE_E * 2 + doff, Bl + gb);
    }
    CP_COMMIT();
}

template <int ACT>
__global__ __launch_bounds__(256) void mma_gemm_kernel(
    const __nv_bfloat16* __restrict__ Ah, const __nv_bfloat16* __restrict__ Al,
    const __nv_bfloat16* __restrict__ Bh, const __nv_bfloat16* __restrict__ Bl,
    const float* __restrict__ bias, float* __restrict__ C, int N, int K)
{
    extern __shared__ __nv_bfloat16 sm[];
    uint32_t sbase = smem_u32(sm);
    int tid = threadIdx.x, lane = tid & 31, wid = tid >> 5;
    int wm = wid & 1, wn = wid >> 1;          // 2 x 4 warp grid
    int row0 = blockIdx.y * 128, col0 = blockIdx.x * 128;

    float acc[4][4][4];
#pragma unroll
    for (int a = 0; a < 4; ++a)
#pragma unroll
        for (int b = 0; b < 4; ++b)
#pragma unroll
            for (int c = 0; c < 4; ++c) acc[a][b][c] = 0.f;

    int tg = lane >> 3, tr = lane & 7;
    // per-lane ldmatrix offsets (elems -> bytes)
    uint32_t aoff = (uint32_t)(((tg & 1) * 8 + tr) * PADR + (tg >> 1) * 8) * 2;
    uint32_t boff = (uint32_t)(((tg >> 1) * 8 + tr) * PADR + (tg & 1) * 8) * 2;

    int nk = K >> 5;
    gemm_load_stage(sbase, 0, 0, row0, col0, tid, K, Ah, Al, Bh, Bl);

    for (int kt = 0; kt < nk; ++kt) {
        if (kt + 1 < nk) {
            gemm_load_stage(sbase, (kt + 1) & 1, kt + 1, row0, col0, tid, K, Ah, Al, Bh, Bl);
            CP_WAIT1();
        } else {
            CP_WAIT0();
        }
        __syncthreads();

        uint32_t so = sbase + (uint32_t)(kt & 1) * STAGE_E * 2;
        uint32_t aH = so, aL = so + TILE_E * 2;
        uint32_t bH = so + 2 * TILE_E * 2, bL = so + 3 * TILE_E * 2;

#pragma unroll
        for (int k16 = 0; k16 < 2; ++k16) {
            uint32_t kadd = (uint32_t)(k16 * 16) * 2;
            uint32_t ah[4][4], al[4][4], bh[2][4], bl[2][4];
#pragma unroll
            for (int mi = 0; mi < 4; ++mi) {
                uint32_t rb = (uint32_t)((wm * 64 + mi * 16) * PADR) * 2;
                ldsm4(ah[mi], aH + rb + aoff + kadd);
            }
#pragma unroll
            for (int nj2 = 0; nj2 < 2; ++nj2) {
                uint32_t nb = (uint32_t)((wn * 32 + nj2 * 16) * PADR) * 2;
                ldsm4(bh[nj2], bH + nb + boff + kadd);
            }
            // pass 1: Ah * Bh
#pragma unroll
            for (int mi = 0; mi < 4; ++mi)
#pragma unroll
                for (int nj = 0; nj < 4; ++nj)
                    mma16816(acc[mi][nj], ah[mi], &bh[nj >> 1][(nj & 1) * 2]);
            // pass 2: Ah * Bl
#pragma unroll
            for (int nj2 = 0; nj2 < 2; ++nj2) {
                uint32_t nb = (uint32_t)((wn * 32 + nj2 * 16) * PADR) * 2;
                ldsm4(bl[nj2], bL + nb + boff + kadd);
            }
#pragma unroll
            for (int mi = 0; mi < 4; ++mi)
#pragma unroll
                for (int nj = 0; nj < 4; ++nj)
                    mma16816(acc[mi][nj], ah[mi], &bl[nj >> 1][(nj & 1) * 2]);
            // pass 3: Al * Bh
#pragma unroll
            for (int mi = 0; mi < 4; ++mi) {
                uint32_t rb = (uint32_t)((wm * 64 + mi * 16) * PADR) * 2;
                ldsm4(al[mi], aL + rb + aoff + kadd);
            }
#pragma unroll
            for (int mi = 0; mi < 4; ++mi)
#pragma unroll
                for (int nj = 0; nj < 4; ++nj)
                    mma16816(acc[mi][nj], al[mi], &bh[nj >> 1][(nj & 1) * 2]);
        }
        __syncthreads();
    }

    // epilogue
    int qr = lane >> 2, qc = (lane & 3) * 2;
#pragma unroll
    for (int mi = 0; mi < 4; ++mi) {
#pragma unroll
        for (int nj = 0; nj < 4; ++nj) {
            int r = row0 + wm * 64 + mi * 16 + qr;
            int c = col0 + wn * 32 + nj * 8 + qc;
            float b0 = bias[c], b1 = bias[c + 1];
            float x0 = acc[mi][nj][0] + b0, x1 = acc[mi][nj][1] + b1;
            float x2 = acc[mi][nj][2] + b0, x3 = acc[mi][nj][3] + b1;
            if (ACT == 1) {
                x0 = 0.5f * x0 * (1.f + erff(x0 * 0.70710678118654752f));
                x1 = 0.5f * x1 * (1.f + erff(x1 * 0.70710678118654752f));
                x2 = 0.5f * x2 * (1.f + erff(x2 * 0.70710678118654752f));
                x3 = 0.5f * x3 * (1.f + erff(x3 * 0.70710678118654752f));
            }
            float2 o0; o0.x = x0; o0.y = x1;
            float2 o1; o1.x = x2; o1.y = x3;
            *(float2*)(C + (size_t)r * N + c) = o0;
            *(float2*)(C + (size_t)(r + 8) * N + c) = o1;
        }
    }
}

// ---------------- sliding-window attention (fp32, fused-QKV input) -----------
__global__ __launch_bounds__(128) void attention_kernel(
    const float* __restrict__ qkv, const int* __restrict__ amask,
    float* __restrict__ o)
{
    __shared__ float ks[64 * 64];
    __shared__ float vs[64 * 64];
    __shared__ int   km[64];

    int c  = blockIdx.x;
    int hh = blockIdx.y;
    int b  = blockIdx.z;
    int p  = threadIdx.x;
    int qpos = c * WIN + p;

    float qr[64];
    {
        const float4* q4 = (const float4*)(qkv + (size_t)(b * SEQ + qpos) * QKVN + hh * HD);
#pragma unroll
        for (int i = 0; i < 16; ++i) {
            float4 t4 = q4[i];
            qr[4 * i + 0] = t4.x * 0.125f;
            qr[4 * i + 1] = t4.y * 0.125f;
            qr[4 * i + 2] = t4.z * 0.125f;
            qr[4 * i + 3] = t4.w * 0.125f;
        }
    }

    float m = -1e30f, l = 0.f;
    float acc[64];
#pragma unroll
    for (int i = 0; i < 64; ++i) acc[i] = 0.f;

    int lo = qpos - WIN, hi = qpos + WIN;
    int kstart = c * WIN - WIN;

    for (int t = 0; t < 6; ++t) {
        int kbase = kstart + t * 64;
        if (kbase < 0 || kbase >= SEQ) continue;
        __syncthreads();
        for (int i = p; i < 64 * 16; i += 128) {
            int jj = i >> 4;
            int d4 = (i & 15) << 2;
            size_t gofs = (size_t)(b * SEQ + kbase + jj) * QKVN + hh * HD + d4;
            *(float4*)(ks + jj * 64 + d4) = *(const float4*)(qkv + gofs + 768);
            *(float4*)(vs + jj * 64 + d4) = *(const float4*)(qkv + gofs + 1536);
        }
        if (p < 64) km[p] = amask[b * SEQ + kbase + p];
        __syncthreads();

        for (int jj = 0; jj < 64; ++jj) {
            int kpos = kbase + jj;
            const float4* k4 = (const float4*)(ks + jj * 64);
            float s = 0.f;
#pragma unroll
            for (int i = 0; i < 16; ++i) {
                float4 kk = k4[i];
                s = fmaf(qr[4 * i + 0], kk.x, s);
                s = fmaf(qr[4 * i + 1], kk.y, s);
                s = fmaf(qr[4 * i + 2], kk.z, s);
                s = fmaf(qr[4 * i + 3], kk.w, s);
            }
            if (kpos < lo || kpos > hi || km[jj] == 0) continue;
            const float4* v4 = (const float4*)(vs + jj * 64);
            if (s > m) {
                float r = __expf(m - s);
                m = s;
                l = fmaf(l, r, 1.f);
#pragma unroll
                for (int i = 0; i < 16; ++i) {
                    float4 vv = v4[i];
                    acc[4 * i + 0] = fmaf(acc[4 * i + 0], r, vv.x);
                    acc[4 * i + 1] = fmaf(acc[4 * i + 1], r, vv.y);
                    acc[4 * i + 2] = fmaf(acc[4 * i + 2], r, vv.z);
                    acc[4 * i + 3] = fmaf(acc[4 * i + 3], r, vv.w);
                }
            } else {
                float pe = __expf(s - m);
                l += pe;
#pragma unroll
                for (int i = 0; i < 16; ++i) {
                    float4 vv = v4[i];
                    acc[4 * i + 0] = fmaf(pe, vv.x, acc[4 * i + 0]);
                    acc[4 * i + 1] = fmaf(pe, vv.y, acc[4 * i + 1]);
                    acc[4 * i + 2] = fmaf(pe, vv.z, acc[4 * i + 2]);
                    acc[4 * i + 3] = fmaf(pe, vv.w, acc[4 * i + 3]);
                }
            }
        }
    }

    float inv = 1.f / l;
    float4* o4 = (float4*)(o + (size_t)(b * SEQ + qpos) * HIDN + hh * HD);
#pragma unroll
    for (int i = 0; i < 16; ++i) {
        float4 t4;
        t4.x = acc[4 * i + 0] * inv;
        t4.y = acc[4 * i + 1] * inv;
        t4.z = acc[4 * i + 2] * inv;
        t4.w = acc[4 * i + 3] * inv;
        o4[i] = t4;
    }
}

// ---------------- classifier -------------------------------------------------
__global__ __launch_bounds__(256) void classifier_kernel(
    const float* __restrict__ Wp, const float* __restrict__ bp,
    float* __restrict__ out)
{
    int t = blockIdx.x, tid = threadIdx.x;
    float s = 0.f, dummy = 0.f;
#pragma unroll
    for (int i = 0; i < 3; ++i) {
        int c = tid + i * 256;
        s += g_h[(size_t)t * HIDN + c] * Wp[c];
    }
    block_allreduce2(s, dummy);
    if (tid == 0) out[t] = 1.f / (1.f + expf(-(s + bp[0])));
}

// ---------------- host launcher ---------------------------------------------
extern "C" void kernel_launch(void* const* d_in, const int* in_sizes, int n_in,
                              void* d_out, int out_size)
{
    (void)in_sizes; (void)n_in; (void)out_size;
    const float* emb  = (const float*)d_in[0];
    const int*   amask= (const int*)  d_in[1];
    const float* pos  = (const float*)d_in[2];
    const float* tok  = (const float*)d_in[3];
    const float* elng = (const float*)d_in[4];
    const float* elnb = (const float*)d_in[5];
    const float* Wq = (const float*)d_in[6],  *bq = (const float*)d_in[7];
    const float* Wk = (const float*)d_in[8],  *bk = (const float*)d_in[9];
    const float* Wv = (const float*)d_in[10], *bv = (const float*)d_in[11];
    const float* Wo = (const float*)d_in[12], *bo = (const float*)d_in[13];
    const float* ln1g = (const float*)d_in[14], *ln1b = (const float*)d_in[15];
    const float* Wi = (const float*)d_in[16], *bi = (const float*)d_in[17];
    const float* Wf = (const float*)d_in[18], *bf = (const float*)d_in[19];
    const float* ln2g = (const float*)d_in[20], *ln2b = (const float*)d_in[21];
    const float* Wp = (const float*)d_in[22], *bp = (const float*)d_in[23];

    static int attr_done = 0;
    if (!attr_done) {
        cudaFuncSetAttribute(mma_gemm_kernel<0>, cudaFuncAttributeMaxDynamicSharedMemorySize, GEMM_SMEM_B);
        cudaFuncSetAttribute(mma_gemm_kernel<1>, cudaFuncAttributeMaxDynamicSharedMemorySize, GEMM_SMEM_B);
        attr_done = 1;
    }

    float *ph, *pqkv, *pa, *pt, *pf, *pbq;
    __nv_bfloat16 *xh, *xl, *wh, *wl;
    cudaGetSymbolAddress((void**)&ph,   g_h);
    cudaGetSymbolAddress((void**)&pqkv, g_qkv);
    cudaGetSymbolAddress((void**)&pa,   g_a);
    cudaGetSymbolAddress((void**)&pt,   g_t);
    cudaGetSymbolAddress((void**)&pf,   g_f);
    cudaGetSymbolAddress((void**)&pbq,  g_bqkv);
    cudaGetSymbolAddress((void**)&xh,   g_xh);
    cudaGetSymbolAddress((void**)&xl,   g_xl);
    cudaGetSymbolAddress((void**)&wh,   g_wh);
    cudaGetSymbolAddress((void**)&wl,   g_wl);

    // weight transpose+split (inputs -> bf16 [N,K] hi/lo), once per launch
    for (int l = 0; l < NLAYER; ++l) {
        size_t wb = (size_t)l * LW;
        const size_t HH = (size_t)HIDN * HIDN;
        wsplit_t_kernel<<<dim3(HIDN/32, HIDN/32), 256>>>(Wq + l*HH, wh + wb + OFF_QKV,            wl + wb + OFF_QKV,            HIDN, HIDN);
        wsplit_t_kernel<<<dim3(HIDN/32, HIDN/32), 256>>>(Wk + l*HH, wh + wb + OFF_QKV + 589824,   wl + wb + OFF_QKV + 589824,   HIDN, HIDN);
        wsplit_t_kernel<<<dim3(HIDN/32, HIDN/32), 256>>>(Wv + l*HH, wh + wb + OFF_QKV + 1179648,  wl + wb + OFF_QKV + 1179648,  HIDN, HIDN);
        wsplit_t_kernel<<<dim3(HIDN/32, HIDN/32), 256>>>(Wo + l*HH, wh + wb + OFF_O,              wl + wb + OFF_O,              HIDN, HIDN);
        wsplit_t_kernel<<<dim3(FFN/32,  HIDN/32), 256>>>(Wi + (size_t)l*HIDN*FFN, wh + wb + OFF_I, wl + wb + OFF_I, HIDN, FFN);
        wsplit_t_kernel<<<dim3(HIDN/32, FFN/32),  256>>>(Wf + (size_t)l*FFN*HIDN, wh + wb + OFF_F, wl + wb + OFF_F, FFN, HIDN);
    }
    bqkv_kernel<<<(NLAYER * QKVN + 255) / 256, 256>>>(bq, bk, bv);

    embed_ln_kernel<<<TOK, 256>>>(emb, pos, tok, elng, elnb);

    const int nH4 = TOK * HIDN / 4;
    const int nF4 = TOK * FFN / 4;

    for (int l = 0; l < NLAYER; ++l) {
        size_t wb = (size_t)l * LW;

        // fused QKV projection
        asplit_kernel<<<(nH4 + 255) / 256, 256>>>(ph, xh, xl, nH4);
        mma_gemm_kernel<0><<<dim3(QKVN/128, TOK/128), 256, GEMM_SMEM_B>>>(
            xh, xl, wh + wb + OFF_QKV, wl + wb + OFF_QKV, pbq + l * QKVN, pqkv, QKVN, HIDN);

        attention_kernel<<<dim3(NCH, NHEAD, BATCH), 128>>>(pqkv, amask, pa);

        // output projection + LN
        asplit_kernel<<<(nH4 + 255) / 256, 256>>>(pa, xh, xl, nH4);
        mma_gemm_kernel<0><<<dim3(HIDN/128, TOK/128), 256, GEMM_SMEM_B>>>(
            xh, xl, wh + wb + OFF_O, wl + wb + OFF_O, bo + l * HIDN, pt, HIDN, HIDN);
        add_ln_kernel<<<TOK, 256>>>(ph, pt, ln1g + l * HIDN, ln1b + l * HIDN, ph);

        // FFN
        asplit_kernel<<<(nH4 + 255) / 256, 256>>>(ph, xh, xl, nH4);
        mma_gemm_kernel<1><<<dim3(FFN/128, TOK/128), 256, GEMM_SMEM_B>>>(
            xh, xl, wh + wb + OFF_I, wl + wb + OFF_I, bi + l * FFN, pf, FFN, HIDN);
        asplit_kernel<<<(nF4 + 255) / 256, 256>>>(pf, xh, xl, nF4);
        mma_gemm_kernel<0><<<dim3(HIDN/128, TOK/128), 256, GEMM_SMEM_B>>>(
            xh, xl, wh + wb + OFF_F, wl + wb + OFF_F, bf + l * HIDN, pt, HIDN, FFN);
        add_ln_kernel<<<TOK, 256>>>(ph, pt, ln2g + l * HIDN, ln2b + l * HIDN, ph);
    }

    classifier_kernel<<<TOK, 256>>>(Wp, bp, (float*)d_out);
}